// round 3
// baseline (speedup 1.0000x reference)
#include <cuda_runtime.h>
#include <math.h>

#define N_NODES 50000
#define N_EDGES 600000
#define N_GRAPHS 128
#define D 128
#define D_EDGE 64
#define N_LAYERS 4
#define BN_EPS 1e-5f

#define EPB 512   // edges per block (edge kernel)
#define NT  64    // nodes per block (node kernel)

// ---------------- scratch (no allocations allowed) ----------------
__device__ float g_agg[N_NODES * D];
__device__ float g_buf0[N_NODES * D];
__device__ float g_buf1[N_NODES * D];
__device__ float g_counts[N_GRAPHS];

// ---------------- zero kernels ----------------
__global__ void zero_agg_kernel() {
    int i = blockIdx.x * blockDim.x + threadIdx.x;
    if (i < N_NODES * D / 4)
        reinterpret_cast<float4*>(g_agg)[i] = make_float4(0.f, 0.f, 0.f, 0.f);
}

__global__ void zero_counts_kernel() {
    if (threadIdx.x < N_GRAPHS) g_counts[threadIdx.x] = 0.f;
}

// ---------------- edge kernel ----------------
// Per edge: e = edge_attr @ W_edge + b ; msg = relu(x[src] + e) ; agg[dst] += msg
// 256 threads = 2 groups of 128; thread owns one output column d, W column in regs.
__global__ __launch_bounds__(256, 2) void edge_kernel(
    const float* __restrict__ x_in,
    const int*   __restrict__ edge_index,
    const float* __restrict__ edge_attr,
    const float* __restrict__ W_edge,
    const float* __restrict__ b_edge,
    int layer)
{
    __shared__ float ea[4][D_EDGE];
    __shared__ int   sd[8];   // [src0,dst0,src1,dst1,...]

    const int t = threadIdx.x;
    const int d = t & 127;
    const int g = t >> 7;

    const float* W = W_edge + (size_t)layer * D_EDGE * D;
    float w[D_EDGE];
#pragma unroll
    for (int k = 0; k < D_EDGE; k++) w[k] = W[k * D + d];
    const float bias = b_edge[layer * D + d];

    int e0    = blockIdx.x * EPB;
    int e_end = min(e0 + EPB, N_EDGES);

    for (; e0 < e_end; e0 += 4) {
        __syncthreads();
        {   // cooperative load of 4 edge_attr rows (256 floats, coalesced)
            int e = e0 + (t >> 6);
            if (e < N_EDGES) ea[t >> 6][t & 63] = edge_attr[(size_t)e * D_EDGE + (t & 63)];
        }
        if (t < 8) {
            int e = e0 + (t >> 1);
            if (e < N_EDGES) sd[t] = edge_index[(size_t)(t & 1) * N_EDGES + e];
        }
        __syncthreads();

#pragma unroll
        for (int j = 0; j < 2; j++) {
            int slot = g * 2 + j;
            int e = e0 + slot;
            if (e < N_EDGES) {
                float acc = bias;
#pragma unroll
                for (int k = 0; k < D_EDGE; k++)
                    acc = fmaf(ea[slot][k], w[k], acc);
                int src = sd[2 * slot];
                int dst = sd[2 * slot + 1];
                float xv = __ldg(x_in + (size_t)src * D + d);
                float m  = fmaxf(acc + xv, 0.f);
                atomicAdd(g_agg + (size_t)dst * D + d, m);
            }
        }
    }
}

// ---------------- node kernel (fused MLP: Lin->BN->ReLU->Lin[->ReLU]) ----------------
__device__ __forceinline__ void mm4(const float* __restrict__ Ws,
                                    const float* __restrict__ ins,
                                    int n0, int d, float bias, float acc[4])
{
    acc[0] = bias; acc[1] = bias; acc[2] = bias; acc[3] = bias;
#pragma unroll 8
    for (int k = 0; k < D; k += 4) {
        float w0 = Ws[(k + 0) * D + d];
        float w1 = Ws[(k + 1) * D + d];
        float w2 = Ws[(k + 2) * D + d];
        float w3 = Ws[(k + 3) * D + d];
#pragma unroll
        for (int j = 0; j < 4; j++) {
            float4 h = *reinterpret_cast<const float4*>(ins + (n0 + j) * D + k);
            acc[j] = fmaf(h.x, w0, acc[j]);
            acc[j] = fmaf(h.y, w1, acc[j]);
            acc[j] = fmaf(h.z, w2, acc[j]);
            acc[j] = fmaf(h.w, w3, acc[j]);
        }
    }
}

__global__ __launch_bounds__(256) void node_kernel(
    const float* __restrict__ x_in,
    float*       __restrict__ x_out,
    const float* __restrict__ W1, const float* __restrict__ b1,
    const float* __restrict__ gamma, const float* __restrict__ beta,
    const float* __restrict__ rm, const float* __restrict__ rv,
    const float* __restrict__ W2, const float* __restrict__ b2,
    int layer, int final_relu)
{
    extern __shared__ float sm[];
    float* Ws = sm;              // 128*128 floats (64 KB)
    float* hs = sm + D * D;      // 64*128 floats (32 KB)
    float* ms = hs + NT * D;     // 64*128 floats (32 KB)

    const int t = threadIdx.x;
    const int d = t & 127;
    const int half = t >> 7;
    const int node0 = blockIdx.x * NT;

    // stage W1
    const float* W1l = W1 + (size_t)layer * D * D;
    for (int i = t; i < D * D; i += 256) Ws[i] = W1l[i];

    // stage h = x + agg
    for (int i = t; i < NT * D; i += 256) {
        int n = node0 + (i >> 7);
        float v = 0.f;
        if (n < N_NODES) {
            size_t idx = (size_t)n * D + (i & 127);
            v = x_in[idx] + g_agg[idx];
        }
        hs[i] = v;
    }

    const float bias1 = b1[layer * D + d];
    const float bias2 = b2[layer * D + d];
    const float scale = gamma[layer * D + d] * rsqrtf(rv[layer * D + d] + BN_EPS);
    const float shift = beta[layer * D + d] - rm[layer * D + d] * scale;
    __syncthreads();

    // phase 1: mid = relu(BN(h @ W1 + b1))
    for (int nb = 0; nb < NT / 2; nb += 4) {
        int n0 = half * (NT / 2) + nb;
        float acc[4];
        mm4(Ws, hs, n0, d, bias1, acc);
#pragma unroll
        for (int j = 0; j < 4; j++)
            ms[(n0 + j) * D + d] = fmaxf(fmaf(acc[j], scale, shift), 0.f);
    }
    __syncthreads();

    // stage W2
    const float* W2l = W2 + (size_t)layer * D * D;
    for (int i = t; i < D * D; i += 256) Ws[i] = W2l[i];
    __syncthreads();

    // phase 2: out = mid @ W2 + b2 (+ relu except last layer)
    for (int nb = 0; nb < NT / 2; nb += 4) {
        int n0 = half * (NT / 2) + nb;
        float acc[4];
        mm4(Ws, ms, n0, d, bias2, acc);
#pragma unroll
        for (int j = 0; j < 4; j++) {
            int n = node0 + n0 + j;
            if (n < N_NODES) {
                float v = acc[j];
                if (final_relu) v = fmaxf(v, 0.f);
                x_out[(size_t)n * D + d] = v;
            }
        }
    }
}

// ---------------- pooling ----------------
__global__ void pool_kernel(const float* __restrict__ x,
                            const int*   __restrict__ batch,
                            float*       __restrict__ out)
{
    int n = blockIdx.x;
    int g = batch[n];
    int t = threadIdx.x;
    atomicAdd(out + (size_t)g * D + t, x[(size_t)n * D + t]);
    if (t == 0) atomicAdd(g_counts + g, 1.0f);
}

__global__ void div_kernel(float* __restrict__ out) {
    int g = blockIdx.x;
    int t = threadIdx.x;
    out[(size_t)g * D + t] /= fmaxf(g_counts[g], 1.0f);
}

// ---------------- launch ----------------
extern "C" void kernel_launch(void* const* d_in, const int* in_sizes, int n_in,
                              void* d_out, int out_size)
{
    const float* x          = (const float*)d_in[0];
    const int*   edge_index = (const int*)  d_in[1];
    const float* edge_attr  = (const float*)d_in[2];
    const int*   batch      = (const int*)  d_in[3];
    const float* W_edge     = (const float*)d_in[4];
    const float* b_edge     = (const float*)d_in[5];
    const float* W1         = (const float*)d_in[6];
    const float* b1         = (const float*)d_in[7];
    const float* gamma      = (const float*)d_in[8];
    const float* beta       = (const float*)d_in[9];
    const float* rm         = (const float*)d_in[10];
    const float* rv         = (const float*)d_in[11];
    const float* W2         = (const float*)d_in[12];
    const float* b2         = (const float*)d_in[13];
    float* out = (float*)d_out;

    cudaFuncSetAttribute((const void*)node_kernel,
                         cudaFuncAttributeMaxDynamicSharedMemorySize, 131072);

    void *pb0, *pb1;
    cudaGetSymbolAddress(&pb0, g_buf0);
    cudaGetSymbolAddress(&pb1, g_buf1);
    float* bufs[2] = { (float*)pb0, (float*)pb1 };

    const int zero_blocks = (N_NODES * D / 4 + 255) / 256;
    const int edge_blocks = (N_EDGES + EPB - 1) / EPB;
    const int node_blocks = (N_NODES + NT - 1) / NT;

    const float* cur = x;
    for (int l = 0; l < N_LAYERS; l++) {
        zero_agg_kernel<<<zero_blocks, 256>>>();
        edge_kernel<<<edge_blocks, 256>>>(cur, edge_index, edge_attr, W_edge, b_edge, l);
        float* nxt = bufs[l & 1];
        node_kernel<<<node_blocks, 256, 131072>>>(cur, nxt, W1, b1, gamma, beta,
                                                  rm, rv, W2, b2, l,
                                                  (l != N_LAYERS - 1) ? 1 : 0);
        cur = nxt;
    }

    zero_counts_kernel<<<1, 128>>>();
    cudaMemsetAsync(out, 0, (size_t)N_GRAPHS * D * sizeof(float));
    pool_kernel<<<N_NODES, 128>>>(cur, batch, out);
    div_kernel<<<N_GRAPHS, 128>>>(out);
}

// round 4
// speedup vs baseline: 1.3136x; 1.3136x over previous
#include <cuda_runtime.h>
#include <math.h>

#define N_NODES 50000
#define N_EDGES 600000
#define N_GRAPHS 128
#define D 128
#define D_EDGE 64
#define N_LAYERS 4
#define BN_EPS 1e-5f

#define EPB 512    // edges per block (edge kernel)
#define ETILE 32   // edges per inner tile
#define NT 64      // nodes per block (node kernel)
#define PCHUNK 400 // nodes per block (pool kernel)

typedef unsigned long long ull;

// packed fp32x2 fma (Blackwell FFMA2)
__device__ __forceinline__ ull fma2(ull a, ull b, ull c) {
    ull d;
    asm("fma.rn.f32x2 %0, %1, %2, %3;" : "=l"(d) : "l"(a), "l"(b), "l"(c));
    return d;
}
// horizontal sum of a packed f32x2
__device__ __forceinline__ float sum2(ull v) {
    float a, b;
    asm("mov.b64 {%0,%1}, %2;" : "=f"(a), "=f"(b) : "l"(v));
    return a + b;
}

// ---------------- scratch (no allocations allowed) ----------------
__device__ float g_agg[N_NODES * D];
__device__ float g_buf0[N_NODES * D];
__device__ float g_buf1[N_NODES * D];
__device__ float g_counts[N_GRAPHS];

// ---------------- zero kernels ----------------
__global__ void zero_agg_kernel() {
    int i = blockIdx.x * blockDim.x + threadIdx.x;
    if (i < N_NODES * D / 4)
        reinterpret_cast<float4*>(g_agg)[i] = make_float4(0.f, 0.f, 0.f, 0.f);
}

__global__ void zero_counts_kernel() {
    if (threadIdx.x < N_GRAPHS) g_counts[threadIdx.x] = 0.f;
}

// ---------------- edge kernel ----------------
// e = edge_attr @ W_edge + b ; msg = relu(x[src] + e) ; agg[dst] += msg
// Thread owns 4 output dims (dq) x 4 edges. FMA2 pairs over K (even/odd sums).
// Warp = 32 dq-threads covering all 128 dims of 4 edges -> coalesced LDG/RED.
__global__ __launch_bounds__(256, 2) void edge_kernel(
    const float* __restrict__ x_in,
    const int*   __restrict__ edge_index,
    const float* __restrict__ edge_attr,
    const float* __restrict__ W_edge,
    const float* __restrict__ b_edge,
    int layer)
{
    __shared__ ull    Wp[(D_EDGE / 2) * D];   // [kk][d] = {W[2kk][d], W[2kk+1][d]}  32KB
    __shared__ float4 ea4[ETILE * 16];        // [e][kq] : 64 floats per edge        8KB
    __shared__ int    sd[2 * ETILE];

    const int t   = threadIdx.x;
    const int dq  = t & 31;   // dim quad: dims 4dq..4dq+3
    const int grp = t >> 5;   // warp id = edge subgroup (4 edges each)

    // stage paired W
    const float* W = W_edge + (size_t)layer * D_EDGE * D;
    float* Wpf = (float*)Wp;
    for (int i = t; i < D_EDGE * D; i += 256) {
        int k = i >> 7, d = i & 127;
        Wpf[((k >> 1) * D + d) * 2 + (k & 1)] = W[i];
    }
    const float4 bias4 = *(const float4*)(b_edge + layer * D + 4 * dq);

    const int e_start = blockIdx.x * EPB;
    const int e_stop  = min(e_start + EPB, N_EDGES);

    for (int e0 = e_start; e0 < e_stop; e0 += ETILE) {
        __syncthreads();
        // load edge_attr tile (32 edges x 16 float4), zero-pad tail
        for (int i = t; i < ETILE * 16; i += 256) {
            int e = e0 + (i >> 4);
            float4 v = make_float4(0.f, 0.f, 0.f, 0.f);
            if (e < N_EDGES)
                v = *(const float4*)(edge_attr + (size_t)e * D_EDGE + (i & 15) * 4);
            ea4[i] = v;
        }
        if (t < 2 * ETILE) {
            int e = e0 + (t >> 1);
            sd[t] = (e < N_EDGES) ? edge_index[(size_t)(t & 1) * N_EDGES + e] : 0;
        }
        __syncthreads();

        ull acc[4][4];
#pragma unroll
        for (int e = 0; e < 4; e++)
#pragma unroll
            for (int j = 0; j < 4; j++) acc[e][j] = 0ull;

#pragma unroll
        for (int kq = 0; kq < 16; kq++) {  // 4 k per iteration (kk = 2kq, 2kq+1)
            ulonglong2 wa = *(ulonglong2*)&Wp[(2 * kq) * D + 4 * dq];         // dims 0,1
            ulonglong2 wb = *(ulonglong2*)&Wp[(2 * kq) * D + 4 * dq + 2];     // dims 2,3
            ulonglong2 wc = *(ulonglong2*)&Wp[(2 * kq + 1) * D + 4 * dq];
            ulonglong2 wd = *(ulonglong2*)&Wp[(2 * kq + 1) * D + 4 * dq + 2];
#pragma unroll
            for (int e = 0; e < 4; e++) {
                ulonglong2 h = *(ulonglong2*)&ea4[(grp * 4 + e) * 16 + kq];
                acc[e][0] = fma2(h.x, wa.x, acc[e][0]);
                acc[e][1] = fma2(h.x, wa.y, acc[e][1]);
                acc[e][2] = fma2(h.x, wb.x, acc[e][2]);
                acc[e][3] = fma2(h.x, wb.y, acc[e][3]);
                acc[e][0] = fma2(h.y, wc.x, acc[e][0]);
                acc[e][1] = fma2(h.y, wc.y, acc[e][1]);
                acc[e][2] = fma2(h.y, wd.x, acc[e][2]);
                acc[e][3] = fma2(h.y, wd.y, acc[e][3]);
            }
        }

#pragma unroll
        for (int e = 0; e < 4; e++) {
            int slot = grp * 4 + e;
            int eg = e0 + slot;
            if (eg < N_EDGES) {
                int src = sd[2 * slot];
                int dst = sd[2 * slot + 1];
                float4 xv = *(const float4*)(x_in + (size_t)src * D + 4 * dq);
                float r0 = fmaxf(sum2(acc[e][0]) + bias4.x + xv.x, 0.f);
                float r1 = fmaxf(sum2(acc[e][1]) + bias4.y + xv.y, 0.f);
                float r2 = fmaxf(sum2(acc[e][2]) + bias4.z + xv.z, 0.f);
                float r3 = fmaxf(sum2(acc[e][3]) + bias4.w + xv.w, 0.f);
                float* p = g_agg + (size_t)dst * D + 4 * dq;
                asm volatile("red.global.add.v4.f32 [%0], {%1,%2,%3,%4};"
                             :: "l"(p), "f"(r0), "f"(r1), "f"(r2), "f"(r3)
                             : "memory");
            }
        }
    }
}

// ---------------- node kernel (fused MLP: Lin->BN->ReLU->Lin[->ReLU]) ----------------
__global__ __launch_bounds__(256) void node_kernel(
    const float* __restrict__ x_in,
    float*       __restrict__ x_out,
    const float* __restrict__ W1, const float* __restrict__ b1,
    const float* __restrict__ gamma, const float* __restrict__ beta,
    const float* __restrict__ rm, const float* __restrict__ rv,
    const float* __restrict__ W2, const float* __restrict__ b2,
    int layer, int final_relu)
{
    extern __shared__ float sm[];
    ull*   Wp = (ull*)sm;                 // 64 kk x 128 d : 64KB
    float* hs = sm + 2 * (D / 2) * D;     // 64 x 128 : 32KB
    float* ms = hs + NT * D;              // 64 x 128 : 32KB

    const int t = threadIdx.x;
    const int d = t & 127;
    const int half = t >> 7;
    const int node0 = blockIdx.x * NT;

    // stage paired W1
    {
        const float* W1l = W1 + (size_t)layer * D * D;
        float* Wpf = (float*)Wp;
        for (int i = t; i < D * D; i += 256) {
            int k = i >> 7, dd = i & 127;
            Wpf[((k >> 1) * D + dd) * 2 + (k & 1)] = W1l[i];
        }
    }
    // stage h = x + agg
    for (int i = t; i < NT * D / 4; i += 256) {
        int n = node0 + (i >> 5);
        float4 v = make_float4(0.f, 0.f, 0.f, 0.f);
        if (n < N_NODES) {
            const float4 a = *(const float4*)(x_in + (size_t)n * D + (i & 31) * 4);
            const float4 b = *(const float4*)(g_agg + (size_t)n * D + (i & 31) * 4);
            v = make_float4(a.x + b.x, a.y + b.y, a.z + b.z, a.w + b.w);
        }
        *(float4*)&hs[i * 4] = v;
    }

    const float bias1 = b1[layer * D + d];
    const float bias2 = b2[layer * D + d];
    const float scale = gamma[layer * D + d] * rsqrtf(rv[layer * D + d] + BN_EPS);
    const float shift = beta[layer * D + d] - rm[layer * D + d] * scale;
    __syncthreads();

    // phase 1: ms = relu(BN(hs @ W1 + b1)); thread = 1 dim x 16 nodes per chunk
#pragma unroll
    for (int c = 0; c < 2; c++) {
        int nb = half * 32 + c * 16;
        ull acc[16];
#pragma unroll
        for (int j = 0; j < 16; j++) acc[j] = 0ull;
#pragma unroll 4
        for (int kq = 0; kq < 32; kq++) {  // 4 k per iter
            ull w0 = Wp[(2 * kq) * D + d];
            ull w1 = Wp[(2 * kq + 1) * D + d];
#pragma unroll
            for (int j = 0; j < 16; j++) {
                ulonglong2 h = *(ulonglong2*)&hs[(nb + j) * D + kq * 4];
                acc[j] = fma2(h.x, w0, acc[j]);
                acc[j] = fma2(h.y, w1, acc[j]);
            }
        }
#pragma unroll
        for (int j = 0; j < 16; j++)
            ms[(nb + j) * D + d] = fmaxf(fmaf(sum2(acc[j]) + bias1, scale, shift), 0.f);
    }
    __syncthreads();

    // restage paired W2
    {
        const float* W2l = W2 + (size_t)layer * D * D;
        float* Wpf = (float*)Wp;
        for (int i = t; i < D * D; i += 256) {
            int k = i >> 7, dd = i & 127;
            Wpf[((k >> 1) * D + dd) * 2 + (k & 1)] = W2l[i];
        }
    }
    __syncthreads();

    // phase 2: out = ms @ W2 + b2 (+ relu except last layer)
#pragma unroll
    for (int c = 0; c < 2; c++) {
        int nb = half * 32 + c * 16;
        ull acc[16];
#pragma unroll
        for (int j = 0; j < 16; j++) acc[j] = 0ull;
#pragma unroll 4
        for (int kq = 0; kq < 32; kq++) {
            ull w0 = Wp[(2 * kq) * D + d];
            ull w1 = Wp[(2 * kq + 1) * D + d];
#pragma unroll
            for (int j = 0; j < 16; j++) {
                ulonglong2 h = *(ulonglong2*)&ms[(nb + j) * D + kq * 4];
                acc[j] = fma2(h.x, w0, acc[j]);
                acc[j] = fma2(h.y, w1, acc[j]);
            }
        }
#pragma unroll
        for (int j = 0; j < 16; j++) {
            int n = node0 + nb + j;
            if (n < N_NODES) {
                float v = sum2(acc[j]) + bias2;
                if (final_relu) v = fmaxf(v, 0.f);
                x_out[(size_t)n * D + d] = v;
            }
        }
    }
}

// ---------------- pooling (batch is sorted: run-length accumulate) ----------------
__global__ void pool_kernel(const float* __restrict__ x,
                            const int*   __restrict__ batch,
                            float*       __restrict__ out)
{
    int n0 = blockIdx.x * PCHUNK;
    int n1 = min(n0 + PCHUNK, N_NODES);
    if (n0 >= N_NODES) return;
    int d = threadIdx.x;  // 128 threads
    float acc = 0.f, cnt = 0.f;
    int cur = batch[n0];
    for (int n = n0; n < n1; n++) {
        int g = batch[n];
        if (g != cur) {
            atomicAdd(out + (size_t)cur * D + d, acc);
            if (d == 0) atomicAdd(g_counts + cur, cnt);
            acc = 0.f; cnt = 0.f; cur = g;
        }
        acc += x[(size_t)n * D + d];
        cnt += 1.f;
    }
    atomicAdd(out + (size_t)cur * D + d, acc);
    if (d == 0) atomicAdd(g_counts + cur, cnt);
}

__global__ void div_kernel(float* __restrict__ out) {
    int g = blockIdx.x;
    int t = threadIdx.x;
    out[(size_t)g * D + t] /= fmaxf(g_counts[g], 1.0f);
}

// ---------------- launch ----------------
extern "C" void kernel_launch(void* const* d_in, const int* in_sizes, int n_in,
                              void* d_out, int out_size)
{
    const float* x          = (const float*)d_in[0];
    const int*   edge_index = (const int*)  d_in[1];
    const float* edge_attr  = (const float*)d_in[2];
    const int*   batch      = (const int*)  d_in[3];
    const float* W_edge     = (const float*)d_in[4];
    const float* b_edge     = (const float*)d_in[5];
    const float* W1         = (const float*)d_in[6];
    const float* b1         = (const float*)d_in[7];
    const float* gamma      = (const float*)d_in[8];
    const float* beta       = (const float*)d_in[9];
    const float* rm         = (const float*)d_in[10];
    const float* rv         = (const float*)d_in[11];
    const float* W2         = (const float*)d_in[12];
    const float* b2         = (const float*)d_in[13];
    float* out = (float*)d_out;

    cudaFuncSetAttribute((const void*)node_kernel,
                         cudaFuncAttributeMaxDynamicSharedMemorySize, 131072);

    void *pb0, *pb1;
    cudaGetSymbolAddress(&pb0, g_buf0);
    cudaGetSymbolAddress(&pb1, g_buf1);
    float* bufs[2] = { (float*)pb0, (float*)pb1 };

    const int zero_blocks = (N_NODES * D / 4 + 255) / 256;
    const int edge_blocks = (N_EDGES + EPB - 1) / EPB;
    const int node_blocks = (N_NODES + NT - 1) / NT;
    const int pool_blocks = (N_NODES + PCHUNK - 1) / PCHUNK;

    const float* cur = x;
    for (int l = 0; l < N_LAYERS; l++) {
        zero_agg_kernel<<<zero_blocks, 256>>>();
        edge_kernel<<<edge_blocks, 256>>>(cur, edge_index, edge_attr, W_edge, b_edge, l);
        float* nxt = bufs[l & 1];
        node_kernel<<<node_blocks, 256, 131072>>>(cur, nxt, W1, b1, gamma, beta,
                                                  rm, rv, W2, b2, l,
                                                  (l != N_LAYERS - 1) ? 1 : 0);
        cur = nxt;
    }

    zero_counts_kernel<<<1, 128>>>();
    cudaMemsetAsync(out, 0, (size_t)N_GRAPHS * D * sizeof(float));
    pool_kernel<<<pool_blocks, 128>>>(cur, batch, out);
    div_kernel<<<N_GRAPHS, 128>>>(out);
}

// round 5
// speedup vs baseline: 1.4394x; 1.0958x over previous
#include <cuda_runtime.h>
#include <math.h>

#define N_NODES 50000
#define N_EDGES 600000
#define N_GRAPHS 128
#define D 128
#define D_EDGE 64
#define N_LAYERS 4
#define BN_EPS 1e-5f

#define EPB 2048   // edges per block -> 293 blocks = 1 wave at occ 2
#define ETILE 64   // edges per inner tile (8 warps x 8 edges)
#define NT 64      // nodes per block (node kernel)
#define PCHUNK 400 // nodes per block (pool kernel)

typedef unsigned long long ull;

// packed fp32x2 fma (Blackwell FFMA2)
__device__ __forceinline__ ull fma2(ull a, ull b, ull c) {
    ull d;
    asm("fma.rn.f32x2 %0, %1, %2, %3;" : "=l"(d) : "l"(a), "l"(b), "l"(c));
    return d;
}
// horizontal sum of a packed f32x2
__device__ __forceinline__ float sum2(ull v) {
    float a, b;
    asm("mov.b64 {%0,%1}, %2;" : "=f"(a), "=f"(b) : "l"(v));
    return a + b;
}

// ---------------- scratch (no allocations allowed) ----------------
__device__ float g_agg[N_NODES * D];   // zero-initialized at load; node kernel re-zeroes
__device__ float g_buf0[N_NODES * D];
__device__ float g_buf1[N_NODES * D];
__device__ float g_counts[N_GRAPHS];

__global__ void zero_counts_kernel() {
    if (threadIdx.x < N_GRAPHS) g_counts[threadIdx.x] = 0.f;
}

// ---------------- edge kernel ----------------
// e = edge_attr @ W_edge + b ; msg = relu(x[src] + e) ; agg[dst] += msg
// Thread owns 4 output dims (dq) x 8 edges. FMA2 pairs over K (even/odd sums).
// W smem reads amortized over 8 edges -> FMA-pipe bound, not smem-crossbar bound.
__global__ __launch_bounds__(256, 2) void edge_kernel(
    const float* __restrict__ x_in,
    const int*   __restrict__ edge_index,
    const float* __restrict__ edge_attr,
    const float* __restrict__ W_edge,
    const float* __restrict__ b_edge,
    int layer)
{
    __shared__ ull    Wp[(D_EDGE / 2) * D];   // [kk][d] = {W[2kk][d], W[2kk+1][d]}  32KB
    __shared__ float4 ea4[ETILE * 16];        // [e][kq] : 64 floats per edge        16KB
    __shared__ int    sd[2 * ETILE];

    const int t   = threadIdx.x;
    const int dq  = t & 31;   // dim quad: dims 4dq..4dq+3
    const int grp = t >> 5;   // warp id = edge subgroup (8 edges each)

    // stage paired W
    const float* W = W_edge + (size_t)layer * D_EDGE * D;
    float* Wpf = (float*)Wp;
    for (int i = t; i < D_EDGE * D; i += 256) {
        int k = i >> 7, d = i & 127;
        Wpf[((k >> 1) * D + d) * 2 + (k & 1)] = W[i];
    }
    const float4 bias4 = *(const float4*)(b_edge + layer * D + 4 * dq);

    const int e_start = blockIdx.x * EPB;
    const int e_stop  = min(e_start + EPB, N_EDGES);

    for (int e0 = e_start; e0 < e_stop; e0 += ETILE) {
        __syncthreads();
        // load edge_attr tile (64 edges x 16 float4), zero-pad tail
        for (int i = t; i < ETILE * 16; i += 256) {
            int e = e0 + (i >> 4);
            float4 v = make_float4(0.f, 0.f, 0.f, 0.f);
            if (e < N_EDGES)
                v = *(const float4*)(edge_attr + (size_t)e * D_EDGE + (i & 15) * 4);
            ea4[i] = v;
        }
        if (t < 2 * ETILE) {
            int e = e0 + (t >> 1);
            sd[t] = (e < N_EDGES) ? edge_index[(size_t)(t & 1) * N_EDGES + e] : 0;
        }
        __syncthreads();

        ull acc[8][4];
#pragma unroll
        for (int e = 0; e < 8; e++)
#pragma unroll
            for (int j = 0; j < 4; j++) acc[e][j] = 0ull;

#pragma unroll 4
        for (int kq = 0; kq < 16; kq++) {  // 4 k per iteration (kk = 2kq, 2kq+1)
            ulonglong2 wa = *(ulonglong2*)&Wp[(2 * kq) * D + 4 * dq];      // k even, dims 0,1
            ulonglong2 wb = *(ulonglong2*)&Wp[(2 * kq) * D + 4 * dq + 2];  // k even, dims 2,3
            ulonglong2 wc = *(ulonglong2*)&Wp[(2 * kq + 1) * D + 4 * dq];
            ulonglong2 wd = *(ulonglong2*)&Wp[(2 * kq + 1) * D + 4 * dq + 2];
#pragma unroll
            for (int e = 0; e < 8; e++) {
                ulonglong2 h = *(ulonglong2*)&ea4[(grp * 8 + e) * 16 + kq];
                acc[e][0] = fma2(h.x, wa.x, acc[e][0]);
                acc[e][1] = fma2(h.x, wa.y, acc[e][1]);
                acc[e][2] = fma2(h.x, wb.x, acc[e][2]);
                acc[e][3] = fma2(h.x, wb.y, acc[e][3]);
                acc[e][0] = fma2(h.y, wc.x, acc[e][0]);
                acc[e][1] = fma2(h.y, wc.y, acc[e][1]);
                acc[e][2] = fma2(h.y, wd.x, acc[e][2]);
                acc[e][3] = fma2(h.y, wd.y, acc[e][3]);
            }
        }

#pragma unroll
        for (int e = 0; e < 8; e++) {
            int slot = grp * 8 + e;
            int eg = e0 + slot;
            if (eg < N_EDGES) {
                int src = sd[2 * slot];
                int dst = sd[2 * slot + 1];
                float4 xv = __ldg((const float4*)(x_in + (size_t)src * D + 4 * dq));
                float r0 = fmaxf(sum2(acc[e][0]) + bias4.x + xv.x, 0.f);
                float r1 = fmaxf(sum2(acc[e][1]) + bias4.y + xv.y, 0.f);
                float r2 = fmaxf(sum2(acc[e][2]) + bias4.z + xv.z, 0.f);
                float r3 = fmaxf(sum2(acc[e][3]) + bias4.w + xv.w, 0.f);
                float* p = g_agg + (size_t)dst * D + 4 * dq;
                asm volatile("red.global.add.v4.f32 [%0], {%1,%2,%3,%4};"
                             :: "l"(p), "f"(r0), "f"(r1), "f"(r2), "f"(r3)
                             : "memory");
            }
        }
    }
}

// ---------------- node kernel (fused MLP: Lin->BN->ReLU->Lin[->ReLU]) ----------------
// Also consumes-and-zeroes g_agg, so no separate zero kernel is needed.
__global__ __launch_bounds__(256) void node_kernel(
    const float* __restrict__ x_in,
    float*       __restrict__ x_out,
    const float* __restrict__ W1, const float* __restrict__ b1,
    const float* __restrict__ gamma, const float* __restrict__ beta,
    const float* __restrict__ rm, const float* __restrict__ rv,
    const float* __restrict__ W2, const float* __restrict__ b2,
    int layer, int final_relu)
{
    extern __shared__ float sm[];
    ull*   Wp = (ull*)sm;                 // 64 kk x 128 d : 64KB
    float* hs = sm + 2 * (D / 2) * D;     // 64 x 128 : 32KB
    float* ms = hs + NT * D;              // 64 x 128 : 32KB

    const int t = threadIdx.x;
    const int d = t & 127;
    const int half = t >> 7;
    const int node0 = blockIdx.x * NT;

    // stage paired W1
    {
        const float* W1l = W1 + (size_t)layer * D * D;
        float* Wpf = (float*)Wp;
        for (int i = t; i < D * D; i += 256) {
            int k = i >> 7, dd = i & 127;
            Wpf[((k >> 1) * D + dd) * 2 + (k & 1)] = W1l[i];
        }
    }
    // stage h = x + agg, and zero g_agg behind us (ready for next layer)
    for (int i = t; i < NT * D / 4; i += 256) {
        int n = node0 + (i >> 5);
        float4 v = make_float4(0.f, 0.f, 0.f, 0.f);
        if (n < N_NODES) {
            size_t idx = (size_t)n * D + (i & 31) * 4;
            const float4 a = *(const float4*)(x_in + idx);
            const float4 b = *(const float4*)(g_agg + idx);
            v = make_float4(a.x + b.x, a.y + b.y, a.z + b.z, a.w + b.w);
            *(float4*)(g_agg + idx) = make_float4(0.f, 0.f, 0.f, 0.f);
        }
        *(float4*)&hs[i * 4] = v;
    }

    const float bias1 = b1[layer * D + d];
    const float bias2 = b2[layer * D + d];
    const float scale = gamma[layer * D + d] * rsqrtf(rv[layer * D + d] + BN_EPS);
    const float shift = beta[layer * D + d] - rm[layer * D + d] * scale;
    __syncthreads();

    // phase 1: ms = relu(BN(hs @ W1 + b1)); thread = 1 dim x 16 nodes per chunk
#pragma unroll
    for (int c = 0; c < 2; c++) {
        int nb = half * 32 + c * 16;
        ull acc[16];
#pragma unroll
        for (int j = 0; j < 16; j++) acc[j] = 0ull;
#pragma unroll 4
        for (int kq = 0; kq < 32; kq++) {  // 4 k per iter
            ull w0 = Wp[(2 * kq) * D + d];
            ull w1 = Wp[(2 * kq + 1) * D + d];
#pragma unroll
            for (int j = 0; j < 16; j++) {
                ulonglong2 h = *(ulonglong2*)&hs[(nb + j) * D + kq * 4];
                acc[j] = fma2(h.x, w0, acc[j]);
                acc[j] = fma2(h.y, w1, acc[j]);
            }
        }
#pragma unroll
        for (int j = 0; j < 16; j++)
            ms[(nb + j) * D + d] = fmaxf(fmaf(sum2(acc[j]) + bias1, scale, shift), 0.f);
    }
    __syncthreads();

    // restage paired W2
    {
        const float* W2l = W2 + (size_t)layer * D * D;
        float* Wpf = (float*)Wp;
        for (int i = t; i < D * D; i += 256) {
            int k = i >> 7, dd = i & 127;
            Wpf[((k >> 1) * D + dd) * 2 + (k & 1)] = W2l[i];
        }
    }
    __syncthreads();

    // phase 2: out = ms @ W2 + b2 (+ relu except last layer)
#pragma unroll
    for (int c = 0; c < 2; c++) {
        int nb = half * 32 + c * 16;
        ull acc[16];
#pragma unroll
        for (int j = 0; j < 16; j++) acc[j] = 0ull;
#pragma unroll 4
        for (int kq = 0; kq < 32; kq++) {
            ull w0 = Wp[(2 * kq) * D + d];
            ull w1 = Wp[(2 * kq + 1) * D + d];
#pragma unroll
            for (int j = 0; j < 16; j++) {
                ulonglong2 h = *(ulonglong2*)&ms[(nb + j) * D + kq * 4];
                acc[j] = fma2(h.x, w0, acc[j]);
                acc[j] = fma2(h.y, w1, acc[j]);
            }
        }
#pragma unroll
        for (int j = 0; j < 16; j++) {
            int n = node0 + nb + j;
            if (n < N_NODES) {
                float v = sum2(acc[j]) + bias2;
                if (final_relu) v = fmaxf(v, 0.f);
                x_out[(size_t)n * D + d] = v;
            }
        }
    }
}

// ---------------- pooling (batch is sorted: run-length accumulate) ----------------
__global__ void pool_kernel(const float* __restrict__ x,
                            const int*   __restrict__ batch,
                            float*       __restrict__ out)
{
    int n0 = blockIdx.x * PCHUNK;
    int n1 = min(n0 + PCHUNK, N_NODES);
    if (n0 >= N_NODES) return;
    int d = threadIdx.x;  // 128 threads
    float acc = 0.f, cnt = 0.f;
    int cur = batch[n0];
    for (int n = n0; n < n1; n++) {
        int g = batch[n];
        if (g != cur) {
            atomicAdd(out + (size_t)cur * D + d, acc);
            if (d == 0) atomicAdd(g_counts + cur, cnt);
            acc = 0.f; cnt = 0.f; cur = g;
        }
        acc += x[(size_t)n * D + d];
        cnt += 1.f;
    }
    atomicAdd(out + (size_t)cur * D + d, acc);
    if (d == 0) atomicAdd(g_counts + cur, cnt);
}

__global__ void div_kernel(float* __restrict__ out) {
    int g = blockIdx.x;
    int t = threadIdx.x;
    out[(size_t)g * D + t] /= fmaxf(g_counts[g], 1.0f);
}

// ---------------- launch ----------------
extern "C" void kernel_launch(void* const* d_in, const int* in_sizes, int n_in,
                              void* d_out, int out_size)
{
    const float* x          = (const float*)d_in[0];
    const int*   edge_index = (const int*)  d_in[1];
    const float* edge_attr  = (const float*)d_in[2];
    const int*   batch      = (const int*)  d_in[3];
    const float* W_edge     = (const float*)d_in[4];
    const float* b_edge     = (const float*)d_in[5];
    const float* W1         = (const float*)d_in[6];
    const float* b1         = (const float*)d_in[7];
    const float* gamma      = (const float*)d_in[8];
    const float* beta       = (const float*)d_in[9];
    const float* rm         = (const float*)d_in[10];
    const float* rv         = (const float*)d_in[11];
    const float* W2         = (const float*)d_in[12];
    const float* b2         = (const float*)d_in[13];
    float* out = (float*)d_out;

    cudaFuncSetAttribute((const void*)node_kernel,
                         cudaFuncAttributeMaxDynamicSharedMemorySize, 131072);

    void *pb0, *pb1;
    cudaGetSymbolAddress(&pb0, g_buf0);
    cudaGetSymbolAddress(&pb1, g_buf1);
    float* bufs[2] = { (float*)pb0, (float*)pb1 };

    const int edge_blocks = (N_EDGES + EPB - 1) / EPB;     // 293
    const int node_blocks = (N_NODES + NT - 1) / NT;
    const int pool_blocks = (N_NODES + PCHUNK - 1) / PCHUNK;

    const float* cur = x;
    for (int l = 0; l < N_LAYERS; l++) {
        edge_kernel<<<edge_blocks, 256>>>(cur, edge_index, edge_attr, W_edge, b_edge, l);
        float* nxt = bufs[l & 1];
        node_kernel<<<node_blocks, 256, 131072>>>(cur, nxt, W1, b1, gamma, beta,
                                                  rm, rv, W2, b2, l,
                                                  (l != N_LAYERS - 1) ? 1 : 0);
        cur = nxt;
    }

    zero_counts_kernel<<<1, 128>>>();
    cudaMemsetAsync(out, 0, (size_t)N_GRAPHS * D * sizeof(float));
    pool_kernel<<<pool_blocks, 128>>>(cur, batch, out);
    div_kernel<<<N_GRAPHS, 128>>>(out);
}

// round 6
// speedup vs baseline: 1.6212x; 1.1263x over previous
#include <cuda_runtime.h>
#include <math.h>

#define N_NODES 50000
#define N_EDGES 600000
#define N_GRAPHS 128
#define D 128
#define D_EDGE 64
#define N_LAYERS 4
#define BN_EPS 1e-5f

#define EPB 2048   // edges per block -> 293 blocks = 1 wave at occ 2
#define ETILE 64   // edges per inner tile (8 warps x 8 edges)
#define NT 64      // nodes per block (node kernel)
#define PCHUNK 400 // nodes per block (pool kernel)

typedef unsigned long long ull;

// packed fp32x2 fma (Blackwell FFMA2)
__device__ __forceinline__ ull fma2(ull a, ull b, ull c) {
    ull d;
    asm("fma.rn.f32x2 %0, %1, %2, %3;" : "=l"(d) : "l"(a), "l"(b), "l"(c));
    return d;
}
// horizontal sum of a packed f32x2
__device__ __forceinline__ float sum2(ull v) {
    float a, b;
    asm("mov.b64 {%0,%1}, %2;" : "=f"(a), "=f"(b) : "l"(v));
    return a + b;
}

// ---------------- scratch (no allocations allowed) ----------------
__device__ float g_agg[N_NODES * D];   // zero at load; node kernel re-zeroes each layer
__device__ float g_buf0[N_NODES * D];
__device__ float g_buf1[N_NODES * D];
__device__ float g_counts[N_GRAPHS];

__global__ void zero_counts_kernel() {
    if (threadIdx.x < N_GRAPHS) g_counts[threadIdx.x] = 0.f;
}

// ---------------- edge kernel ----------------
// e = edge_attr @ W_edge + b ; msg = relu(x[src] + e) ; agg[dst] += msg
__global__ __launch_bounds__(256, 2) void edge_kernel(
    const float* __restrict__ x_in,
    const int*   __restrict__ edge_index,
    const float* __restrict__ edge_attr,
    const float* __restrict__ W_edge,
    const float* __restrict__ b_edge,
    int layer)
{
    __shared__ ull    Wp[(D_EDGE / 2) * D];   // paired-k W : 32KB
    __shared__ float4 ea4[ETILE * 16];        // 64 edges x 64 floats : 16KB
    __shared__ int    sd[2 * ETILE];

    const int t   = threadIdx.x;
    const int dq  = t & 31;   // dims 4dq..4dq+3
    const int grp = t >> 5;   // warp id = 8-edge subgroup

    const float* W = W_edge + (size_t)layer * D_EDGE * D;
    float* Wpf = (float*)Wp;
    for (int i = t; i < D_EDGE * D; i += 256) {
        int k = i >> 7, d = i & 127;
        Wpf[((k >> 1) * D + d) * 2 + (k & 1)] = W[i];
    }
    const float4 bias4 = *(const float4*)(b_edge + layer * D + 4 * dq);

    const int e_start = blockIdx.x * EPB;
    const int e_stop  = min(e_start + EPB, N_EDGES);

    for (int e0 = e_start; e0 < e_stop; e0 += ETILE) {
        __syncthreads();
        for (int i = t; i < ETILE * 16; i += 256) {
            int e = e0 + (i >> 4);
            float4 v = make_float4(0.f, 0.f, 0.f, 0.f);
            if (e < N_EDGES)
                v = *(const float4*)(edge_attr + (size_t)e * D_EDGE + (i & 15) * 4);
            ea4[i] = v;
        }
        if (t < 2 * ETILE) {
            int e = e0 + (t >> 1);
            sd[t] = (e < N_EDGES) ? edge_index[(size_t)(t & 1) * N_EDGES + e] : 0;
        }
        __syncthreads();

        ull acc[8][4];
#pragma unroll
        for (int e = 0; e < 8; e++)
#pragma unroll
            for (int j = 0; j < 4; j++) acc[e][j] = 0ull;

#pragma unroll 4
        for (int kq = 0; kq < 16; kq++) {
            ulonglong2 wa = *(ulonglong2*)&Wp[(2 * kq) * D + 4 * dq];
            ulonglong2 wb = *(ulonglong2*)&Wp[(2 * kq) * D + 4 * dq + 2];
            ulonglong2 wc = *(ulonglong2*)&Wp[(2 * kq + 1) * D + 4 * dq];
            ulonglong2 wd = *(ulonglong2*)&Wp[(2 * kq + 1) * D + 4 * dq + 2];
#pragma unroll
            for (int e = 0; e < 8; e++) {
                ulonglong2 h = *(ulonglong2*)&ea4[(grp * 8 + e) * 16 + kq];
                acc[e][0] = fma2(h.x, wa.x, acc[e][0]);
                acc[e][1] = fma2(h.x, wa.y, acc[e][1]);
                acc[e][2] = fma2(h.x, wb.x, acc[e][2]);
                acc[e][3] = fma2(h.x, wb.y, acc[e][3]);
                acc[e][0] = fma2(h.y, wc.x, acc[e][0]);
                acc[e][1] = fma2(h.y, wc.y, acc[e][1]);
                acc[e][2] = fma2(h.y, wd.x, acc[e][2]);
                acc[e][3] = fma2(h.y, wd.y, acc[e][3]);
            }
        }

#pragma unroll
        for (int e = 0; e < 8; e++) {
            int slot = grp * 8 + e;
            int eg = e0 + slot;
            if (eg < N_EDGES) {
                int src = sd[2 * slot];
                int dst = sd[2 * slot + 1];
                float4 xv = __ldg((const float4*)(x_in + (size_t)src * D + 4 * dq));
                float r0 = fmaxf(sum2(acc[e][0]) + bias4.x + xv.x, 0.f);
                float r1 = fmaxf(sum2(acc[e][1]) + bias4.y + xv.y, 0.f);
                float r2 = fmaxf(sum2(acc[e][2]) + bias4.z + xv.z, 0.f);
                float r3 = fmaxf(sum2(acc[e][3]) + bias4.w + xv.w, 0.f);
                float* p = g_agg + (size_t)dst * D + 4 * dq;
                asm volatile("red.global.add.v4.f32 [%0], {%1,%2,%3,%4};"
                             :: "l"(p), "f"(r0), "f"(r1), "f"(r2), "f"(r3)
                             : "memory");
            }
        }
    }
}

// ---------------- node kernel (fused MLP: Lin->BN->ReLU->Lin[->ReLU]) ----------------
// smem = Wp 64KB + hs 32KB = 96KB -> 2 blocks/SM (16 warps).
// Thread = (dim-pair dp, node-quarter q): 2 dims x 16 nodes, 64 FMA2 per kq-iter.
// Mid activations live in registers between phases; hs is reused for them.
// Also consumes-and-zeroes g_agg (no separate zero kernel).
__global__ __launch_bounds__(256, 2) void node_kernel(
    const float* __restrict__ x_in,
    float*       __restrict__ x_out,
    const float* __restrict__ W1, const float* __restrict__ b1,
    const float* __restrict__ gamma, const float* __restrict__ beta,
    const float* __restrict__ rm, const float* __restrict__ rv,
    const float* __restrict__ W2, const float* __restrict__ b2,
    int layer, int final_relu)
{
    extern __shared__ float sm[];
    ull*   Wp = (ull*)sm;                 // 64 kk x 128 d paired : 64KB
    float* hs = sm + (D / 2) * D * 2;     // 64 nodes x 128 : 32KB

    const int t  = threadIdx.x;
    const int dp = t & 63;                // dims 2dp, 2dp+1
    const int q  = t >> 6;                // node quarter
    const int nb = q * 16;
    const int node0 = blockIdx.x * NT;

    // stage paired W1
    {
        const float* W1l = W1 + (size_t)layer * D * D;
        float* Wpf = (float*)Wp;
        for (int i = t; i < D * D; i += 256) {
            int k = i >> 7, dd = i & 127;
            Wpf[((k >> 1) * D + dd) * 2 + (k & 1)] = W1l[i];
        }
    }
    // stage h = x + agg, zero g_agg behind us
    for (int i = t; i < NT * D / 4; i += 256) {
        int n = node0 + (i >> 5);
        float4 v = make_float4(0.f, 0.f, 0.f, 0.f);
        if (n < N_NODES) {
            size_t idx = (size_t)n * D + (i & 31) * 4;
            const float4 a = *(const float4*)(x_in + idx);
            const float4 b = *(const float4*)(g_agg + idx);
            v = make_float4(a.x + b.x, a.y + b.y, a.z + b.z, a.w + b.w);
            *(float4*)(g_agg + idx) = make_float4(0.f, 0.f, 0.f, 0.f);
        }
        *(float4*)&hs[i * 4] = v;
    }

    const float2 b1v = *(const float2*)(b1 + layer * D + 2 * dp);
    const float2 b2v = *(const float2*)(b2 + layer * D + 2 * dp);
    const float2 gv  = *(const float2*)(gamma + layer * D + 2 * dp);
    const float2 bv  = *(const float2*)(beta + layer * D + 2 * dp);
    const float2 rmv = *(const float2*)(rm + layer * D + 2 * dp);
    const float2 rvv = *(const float2*)(rv + layer * D + 2 * dp);
    const float sc0 = gv.x * rsqrtf(rvv.x + BN_EPS);
    const float sc1 = gv.y * rsqrtf(rvv.y + BN_EPS);
    const float sh0 = bv.x - rmv.x * sc0;
    const float sh1 = bv.y - rmv.y * sc1;
    __syncthreads();

    // ---- phase 1: mid = relu(BN(hs @ W1 + b1)) ----
    ull acc[16][2];
#pragma unroll
    for (int j = 0; j < 16; j++) { acc[j][0] = 0ull; acc[j][1] = 0ull; }
#pragma unroll 4
    for (int kq = 0; kq < 32; kq++) {
        ulonglong2 w0 = *(ulonglong2*)&Wp[(2 * kq) * D + 2 * dp];
        ulonglong2 w1 = *(ulonglong2*)&Wp[(2 * kq + 1) * D + 2 * dp];
#pragma unroll
        for (int j = 0; j < 16; j++) {
            ulonglong2 h = *(ulonglong2*)&hs[(nb + j) * D + kq * 4];
            acc[j][0] = fma2(h.x, w0.x, acc[j][0]);
            acc[j][1] = fma2(h.x, w0.y, acc[j][1]);
            acc[j][0] = fma2(h.y, w1.x, acc[j][0]);
            acc[j][1] = fma2(h.y, w1.y, acc[j][1]);
        }
    }
    float mid[16][2];
#pragma unroll
    for (int j = 0; j < 16; j++) {
        mid[j][0] = fmaxf(fmaf(sum2(acc[j][0]) + b1v.x, sc0, sh0), 0.f);
        mid[j][1] = fmaxf(fmaf(sum2(acc[j][1]) + b1v.y, sc1, sh1), 0.f);
    }
    __syncthreads();

    // write mid into hs; restage paired W2
#pragma unroll
    for (int j = 0; j < 16; j++)
        *(float2*)&hs[(nb + j) * D + 2 * dp] = make_float2(mid[j][0], mid[j][1]);
    {
        const float* W2l = W2 + (size_t)layer * D * D;
        float* Wpf = (float*)Wp;
        for (int i = t; i < D * D; i += 256) {
            int k = i >> 7, dd = i & 127;
            Wpf[((k >> 1) * D + dd) * 2 + (k & 1)] = W2l[i];
        }
    }
    __syncthreads();

    // ---- phase 2: out = mid @ W2 + b2 (+ relu except last layer) ----
#pragma unroll
    for (int j = 0; j < 16; j++) { acc[j][0] = 0ull; acc[j][1] = 0ull; }
#pragma unroll 4
    for (int kq = 0; kq < 32; kq++) {
        ulonglong2 w0 = *(ulonglong2*)&Wp[(2 * kq) * D + 2 * dp];
        ulonglong2 w1 = *(ulonglong2*)&Wp[(2 * kq + 1) * D + 2 * dp];
#pragma unroll
        for (int j = 0; j < 16; j++) {
            ulonglong2 h = *(ulonglong2*)&hs[(nb + j) * D + kq * 4];
            acc[j][0] = fma2(h.x, w0.x, acc[j][0]);
            acc[j][1] = fma2(h.x, w0.y, acc[j][1]);
            acc[j][0] = fma2(h.y, w1.x, acc[j][0]);
            acc[j][1] = fma2(h.y, w1.y, acc[j][1]);
        }
    }
#pragma unroll
    for (int j = 0; j < 16; j++) {
        int n = node0 + nb + j;
        if (n < N_NODES) {
            float v0 = sum2(acc[j][0]) + b2v.x;
            float v1 = sum2(acc[j][1]) + b2v.y;
            if (final_relu) { v0 = fmaxf(v0, 0.f); v1 = fmaxf(v1, 0.f); }
            *(float2*)(x_out + (size_t)n * D + 2 * dp) = make_float2(v0, v1);
        }
    }
}

// ---------------- pooling (batch is sorted: run-length accumulate) ----------------
__global__ void pool_kernel(const float* __restrict__ x,
                            const int*   __restrict__ batch,
                            float*       __restrict__ out)
{
    int n0 = blockIdx.x * PCHUNK;
    int n1 = min(n0 + PCHUNK, N_NODES);
    if (n0 >= N_NODES) return;
    int d = threadIdx.x;  // 128 threads
    float acc = 0.f, cnt = 0.f;
    int cur = batch[n0];
    for (int n = n0; n < n1; n++) {
        int g = batch[n];
        if (g != cur) {
            atomicAdd(out + (size_t)cur * D + d, acc);
            if (d == 0) atomicAdd(g_counts + cur, cnt);
            acc = 0.f; cnt = 0.f; cur = g;
        }
        acc += x[(size_t)n * D + d];
        cnt += 1.f;
    }
    atomicAdd(out + (size_t)cur * D + d, acc);
    if (d == 0) atomicAdd(g_counts + cur, cnt);
}

__global__ void div_kernel(float* __restrict__ out) {
    int g = blockIdx.x;
    int t = threadIdx.x;
    out[(size_t)g * D + t] /= fmaxf(g_counts[g], 1.0f);
}

// ---------------- launch ----------------
extern "C" void kernel_launch(void* const* d_in, const int* in_sizes, int n_in,
                              void* d_out, int out_size)
{
    const float* x          = (const float*)d_in[0];
    const int*   edge_index = (const int*)  d_in[1];
    const float* edge_attr  = (const float*)d_in[2];
    const int*   batch      = (const int*)  d_in[3];
    const float* W_edge     = (const float*)d_in[4];
    const float* b_edge     = (const float*)d_in[5];
    const float* W1         = (const float*)d_in[6];
    const float* b1         = (const float*)d_in[7];
    const float* gamma      = (const float*)d_in[8];
    const float* beta       = (const float*)d_in[9];
    const float* rm         = (const float*)d_in[10];
    const float* rv         = (const float*)d_in[11];
    const float* W2         = (const float*)d_in[12];
    const float* b2         = (const float*)d_in[13];
    float* out = (float*)d_out;

    cudaFuncSetAttribute((const void*)node_kernel,
                         cudaFuncAttributeMaxDynamicSharedMemorySize, 98304);

    void *pb0, *pb1;
    cudaGetSymbolAddress(&pb0, g_buf0);
    cudaGetSymbolAddress(&pb1, g_buf1);
    float* bufs[2] = { (float*)pb0, (float*)pb1 };

    const int edge_blocks = (N_EDGES + EPB - 1) / EPB;
    const int node_blocks = (N_NODES + NT - 1) / NT;
    const int pool_blocks = (N_NODES + PCHUNK - 1) / PCHUNK;

    const float* cur = x;
    for (int l = 0; l < N_LAYERS; l++) {
        edge_kernel<<<edge_blocks, 256>>>(cur, edge_index, edge_attr, W_edge, b_edge, l);
        float* nxt = bufs[l & 1];
        node_kernel<<<node_blocks, 256, 98304>>>(cur, nxt, W1, b1, gamma, beta,
                                                 rm, rv, W2, b2, l,
                                                 (l != N_LAYERS - 1) ? 1 : 0);
        cur = nxt;
    }

    zero_counts_kernel<<<1, 128>>>();
    cudaMemsetAsync(out, 0, (size_t)N_GRAPHS * D * sizeof(float));
    pool_kernel<<<pool_blocks, 128>>>(cur, batch, out);
    div_kernel<<<N_GRAPHS, 128>>>(out);
}

// round 7
// speedup vs baseline: 1.6247x; 1.0022x over previous
#include <cuda_runtime.h>
#include <math.h>

#define N_NODES 50000
#define N_EDGES 600000
#define N_GRAPHS 128
#define D 128
#define D_EDGE 64
#define N_LAYERS 4
#define BN_EPS 1e-5f

#define EPB 2048   // edges per block -> 293 blocks
#define ETILE 64   // edges per inner tile (8 warps x 8 edges)
#define NT 64      // nodes per block (node kernel)
#define PCHUNK 400 // nodes per block (pool kernel)

typedef unsigned long long ull;

// packed fp32x2 fma (Blackwell FFMA2)
__device__ __forceinline__ ull fma2(ull a, ull b, ull c) {
    ull d;
    asm("fma.rn.f32x2 %0, %1, %2, %3;" : "=l"(d) : "l"(a), "l"(b), "l"(c));
    return d;
}
// horizontal sum of a packed f32x2
__device__ __forceinline__ float sum2(ull v) {
    float a, b;
    asm("mov.b64 {%0,%1}, %2;" : "=f"(a), "=f"(b) : "l"(v));
    return a + b;
}

// ---------------- scratch (no allocations allowed) ----------------
__device__ float g_agg[N_NODES * D];   // zero at load; node kernel re-zeroes each layer
__device__ float g_buf0[N_NODES * D];
__device__ float g_buf1[N_NODES * D];
__device__ float g_counts[N_GRAPHS];

__global__ void zero_counts_kernel() {
    if (threadIdx.x < N_GRAPHS) g_counts[threadIdx.x] = 0.f;
}

// ---------------- edge kernel ----------------
// e = edge_attr @ W_edge + b ; msg = relu(x[src] + e) ; agg[dst] += msg
// Thread: 4 dims x 8 edges. kq loop NOT unrolled (reg budget 128); two 4-edge waves.
__global__ __launch_bounds__(256, 2) void edge_kernel(
    const float* __restrict__ x_in,
    const int*   __restrict__ edge_index,
    const float* __restrict__ edge_attr,
    const float* __restrict__ W_edge,
    const float* __restrict__ b_edge,
    int layer)
{
    __shared__ ull    Wp[(D_EDGE / 2) * D];   // paired-k W : 32KB
    __shared__ float4 ea4[ETILE * 16];        // 64 edges x 64 floats : 16KB
    __shared__ int    sd[2 * ETILE];

    const int t   = threadIdx.x;
    const int dq  = t & 31;   // dims 4dq..4dq+3
    const int grp = t >> 5;   // warp id = 8-edge subgroup

    const float* W = W_edge + (size_t)layer * D_EDGE * D;
    float* Wpf = (float*)Wp;
    for (int i = t; i < D_EDGE * D; i += 256) {
        int k = i >> 7, d = i & 127;
        Wpf[((k >> 1) * D + d) * 2 + (k & 1)] = W[i];
    }
    const float4 bias4 = *(const float4*)(b_edge + layer * D + 4 * dq);

    const int e_start = blockIdx.x * EPB;
    const int e_stop  = min(e_start + EPB, N_EDGES);

    for (int e0 = e_start; e0 < e_stop; e0 += ETILE) {
        __syncthreads();
        for (int i = t; i < ETILE * 16; i += 256) {
            int e = e0 + (i >> 4);
            float4 v = make_float4(0.f, 0.f, 0.f, 0.f);
            if (e < N_EDGES)
                v = *(const float4*)(edge_attr + (size_t)e * D_EDGE + (i & 15) * 4);
            ea4[i] = v;
        }
        if (t < 2 * ETILE) {
            int e = e0 + (t >> 1);
            sd[t] = (e < N_EDGES) ? edge_index[(size_t)(t & 1) * N_EDGES + e] : 0;
        }
        __syncthreads();

        ull acc[8][4];
#pragma unroll
        for (int e = 0; e < 8; e++)
#pragma unroll
            for (int j = 0; j < 4; j++) acc[e][j] = 0ull;

        for (int kq = 0; kq < 16; kq++) {  // NOT unrolled: fits 128-reg budget
            ulonglong2 wa = *(ulonglong2*)&Wp[(2 * kq) * D + 4 * dq];
            ulonglong2 wb = *(ulonglong2*)&Wp[(2 * kq) * D + 4 * dq + 2];
            ulonglong2 wc = *(ulonglong2*)&Wp[(2 * kq + 1) * D + 4 * dq];
            ulonglong2 wd = *(ulonglong2*)&Wp[(2 * kq + 1) * D + 4 * dq + 2];
#pragma unroll
            for (int w = 0; w < 2; w++) {          // two waves of 4 edges
                ulonglong2 h[4];
#pragma unroll
                for (int e = 0; e < 4; e++)
                    h[e] = *(ulonglong2*)&ea4[(grp * 8 + w * 4 + e) * 16 + kq];
#pragma unroll
                for (int e = 0; e < 4; e++) {
                    int s = w * 4 + e;
                    acc[s][0] = fma2(h[e].x, wa.x, acc[s][0]);
                    acc[s][1] = fma2(h[e].x, wa.y, acc[s][1]);
                    acc[s][2] = fma2(h[e].x, wb.x, acc[s][2]);
                    acc[s][3] = fma2(h[e].x, wb.y, acc[s][3]);
                    acc[s][0] = fma2(h[e].y, wc.x, acc[s][0]);
                    acc[s][1] = fma2(h[e].y, wc.y, acc[s][1]);
                    acc[s][2] = fma2(h[e].y, wd.x, acc[s][2]);
                    acc[s][3] = fma2(h[e].y, wd.y, acc[s][3]);
                }
            }
        }

#pragma unroll
        for (int e = 0; e < 8; e++) {
            int slot = grp * 8 + e;
            int eg = e0 + slot;
            if (eg < N_EDGES) {
                int src = sd[2 * slot];
                int dst = sd[2 * slot + 1];
                float4 xv = __ldg((const float4*)(x_in + (size_t)src * D + 4 * dq));
                float r0 = fmaxf(sum2(acc[e][0]) + bias4.x + xv.x, 0.f);
                float r1 = fmaxf(sum2(acc[e][1]) + bias4.y + xv.y, 0.f);
                float r2 = fmaxf(sum2(acc[e][2]) + bias4.z + xv.z, 0.f);
                float r3 = fmaxf(sum2(acc[e][3]) + bias4.w + xv.w, 0.f);
                float* p = g_agg + (size_t)dst * D + 4 * dq;
                asm volatile("red.global.add.v4.f32 [%0], {%1,%2,%3,%4};"
                             :: "l"(p), "f"(r0), "f"(r1), "f"(r2), "f"(r3)
                             : "memory");
            }
        }
    }
}

// ---------------- node kernel (fused MLP: Lin->BN->ReLU->Lin[->ReLU]) ----------------
// smem 96KB -> 2 blocks/SM; regs capped 128 (regfile-exact). kq loop NOT unrolled;
// body = two 8-node waves so the live set fits without spills.
__global__ __launch_bounds__(256, 2) void node_kernel(
    const float* __restrict__ x_in,
    float*       __restrict__ x_out,
    const float* __restrict__ W1, const float* __restrict__ b1,
    const float* __restrict__ gamma, const float* __restrict__ beta,
    const float* __restrict__ rm, const float* __restrict__ rv,
    const float* __restrict__ W2, const float* __restrict__ b2,
    int layer, int final_relu)
{
    extern __shared__ float sm[];
    ull*   Wp = (ull*)sm;                 // 64 kk x 128 d paired : 64KB
    float* hs = sm + (D / 2) * D * 2;     // 64 nodes x 128 : 32KB

    const int t  = threadIdx.x;
    const int dp = t & 63;                // dims 2dp, 2dp+1
    const int q  = t >> 6;                // node quarter
    const int nb = q * 16;
    const int node0 = blockIdx.x * NT;

    // stage paired W1
    {
        const float* W1l = W1 + (size_t)layer * D * D;
        float* Wpf = (float*)Wp;
        for (int i = t; i < D * D; i += 256) {
            int k = i >> 7, dd = i & 127;
            Wpf[((k >> 1) * D + dd) * 2 + (k & 1)] = W1l[i];
        }
    }
    // stage h = x + agg, zero g_agg behind us
    for (int i = t; i < NT * D / 4; i += 256) {
        int n = node0 + (i >> 5);
        float4 v = make_float4(0.f, 0.f, 0.f, 0.f);
        if (n < N_NODES) {
            size_t idx = (size_t)n * D + (i & 31) * 4;
            const float4 a = *(const float4*)(x_in + idx);
            const float4 b = *(const float4*)(g_agg + idx);
            v = make_float4(a.x + b.x, a.y + b.y, a.z + b.z, a.w + b.w);
            *(float4*)(g_agg + idx) = make_float4(0.f, 0.f, 0.f, 0.f);
        }
        *(float4*)&hs[i * 4] = v;
    }

    const float2 b1v = *(const float2*)(b1 + layer * D + 2 * dp);
    const float2 b2v = *(const float2*)(b2 + layer * D + 2 * dp);
    const float2 gv  = *(const float2*)(gamma + layer * D + 2 * dp);
    const float2 bv  = *(const float2*)(beta + layer * D + 2 * dp);
    const float2 rmv = *(const float2*)(rm + layer * D + 2 * dp);
    const float2 rvv = *(const float2*)(rv + layer * D + 2 * dp);
    const float sc0 = gv.x * rsqrtf(rvv.x + BN_EPS);
    const float sc1 = gv.y * rsqrtf(rvv.y + BN_EPS);
    const float sh0 = bv.x - rmv.x * sc0;
    const float sh1 = bv.y - rmv.y * sc1;
    __syncthreads();

    // ---- phase 1: mid = relu(BN(hs @ W1 + b1)) ----
    ull acc[16][2];
#pragma unroll
    for (int j = 0; j < 16; j++) { acc[j][0] = 0ull; acc[j][1] = 0ull; }
    for (int kq = 0; kq < 32; kq++) {
        ulonglong2 w0 = *(ulonglong2*)&Wp[(2 * kq) * D + 2 * dp];
        ulonglong2 w1 = *(ulonglong2*)&Wp[(2 * kq + 1) * D + 2 * dp];
#pragma unroll
        for (int w = 0; w < 2; w++) {          // two waves of 8 nodes
            ulonglong2 h[8];
#pragma unroll
            for (int j = 0; j < 8; j++)
                h[j] = *(ulonglong2*)&hs[(nb + w * 8 + j) * D + kq * 4];
#pragma unroll
            for (int j = 0; j < 8; j++) {
                int s = w * 8 + j;
                acc[s][0] = fma2(h[j].x, w0.x, acc[s][0]);
                acc[s][1] = fma2(h[j].x, w0.y, acc[s][1]);
                acc[s][0] = fma2(h[j].y, w1.x, acc[s][0]);
                acc[s][1] = fma2(h[j].y, w1.y, acc[s][1]);
            }
        }
    }
    float mid[16][2];
#pragma unroll
    for (int j = 0; j < 16; j++) {
        mid[j][0] = fmaxf(fmaf(sum2(acc[j][0]) + b1v.x, sc0, sh0), 0.f);
        mid[j][1] = fmaxf(fmaf(sum2(acc[j][1]) + b1v.y, sc1, sh1), 0.f);
    }
    __syncthreads();

    // write mid into hs; restage paired W2
#pragma unroll
    for (int j = 0; j < 16; j++)
        *(float2*)&hs[(nb + j) * D + 2 * dp] = make_float2(mid[j][0], mid[j][1]);
    {
        const float* W2l = W2 + (size_t)layer * D * D;
        float* Wpf = (float*)Wp;
        for (int i = t; i < D * D; i += 256) {
            int k = i >> 7, dd = i & 127;
            Wpf[((k >> 1) * D + dd) * 2 + (k & 1)] = W2l[i];
        }
    }
    __syncthreads();

    // ---- phase 2: out = mid @ W2 + b2 (+ relu except last layer) ----
#pragma unroll
    for (int j = 0; j < 16; j++) { acc[j][0] = 0ull; acc[j][1] = 0ull; }
    for (int kq = 0; kq < 32; kq++) {
        ulonglong2 w0 = *(ulonglong2*)&Wp[(2 * kq) * D + 2 * dp];
        ulonglong2 w1 = *(ulonglong2*)&Wp[(2 * kq + 1) * D + 2 * dp];
#pragma unroll
        for (int w = 0; w < 2; w++) {
            ulonglong2 h[8];
#pragma unroll
            for (int j = 0; j < 8; j++)
                h[j] = *(ulonglong2*)&hs[(nb + w * 8 + j) * D + kq * 4];
#pragma unroll
            for (int j = 0; j < 8; j++) {
                int s = w * 8 + j;
                acc[s][0] = fma2(h[j].x, w0.x, acc[s][0]);
                acc[s][1] = fma2(h[j].x, w0.y, acc[s][1]);
                acc[s][0] = fma2(h[j].y, w1.x, acc[s][0]);
                acc[s][1] = fma2(h[j].y, w1.y, acc[s][1]);
            }
        }
    }
#pragma unroll
    for (int j = 0; j < 16; j++) {
        int n = node0 + nb + j;
        if (n < N_NODES) {
            float v0 = sum2(acc[j][0]) + b2v.x;
            float v1 = sum2(acc[j][1]) + b2v.y;
            if (final_relu) { v0 = fmaxf(v0, 0.f); v1 = fmaxf(v1, 0.f); }
            *(float2*)(x_out + (size_t)n * D + 2 * dp) = make_float2(v0, v1);
        }
    }
}

// ---------------- pooling (batch is sorted: run-length accumulate) ----------------
__global__ void pool_kernel(const float* __restrict__ x,
                            const int*   __restrict__ batch,
                            float*       __restrict__ out)
{
    int n0 = blockIdx.x * PCHUNK;
    int n1 = min(n0 + PCHUNK, N_NODES);
    if (n0 >= N_NODES) return;
    int d = threadIdx.x;  // 128 threads
    float acc = 0.f, cnt = 0.f;
    int cur = batch[n0];
    for (int n = n0; n < n1; n++) {
        int g = batch[n];
        if (g != cur) {
            atomicAdd(out + (size_t)cur * D + d, acc);
            if (d == 0) atomicAdd(g_counts + cur, cnt);
            acc = 0.f; cnt = 0.f; cur = g;
        }
        acc += x[(size_t)n * D + d];
        cnt += 1.f;
    }
    atomicAdd(out + (size_t)cur * D + d, acc);
    if (d == 0) atomicAdd(g_counts + cur, cnt);
}

__global__ void div_kernel(float* __restrict__ out) {
    int g = blockIdx.x;
    int t = threadIdx.x;
    out[(size_t)g * D + t] /= fmaxf(g_counts[g], 1.0f);
}

// ---------------- launch ----------------
extern "C" void kernel_launch(void* const* d_in, const int* in_sizes, int n_in,
                              void* d_out, int out_size)
{
    const float* x          = (const float*)d_in[0];
    const int*   edge_index = (const int*)  d_in[1];
    const float* edge_attr  = (const float*)d_in[2];
    const int*   batch      = (const int*)  d_in[3];
    const float* W_edge     = (const float*)d_in[4];
    const float* b_edge     = (const float*)d_in[5];
    const float* W1         = (const float*)d_in[6];
    const float* b1         = (const float*)d_in[7];
    const float* gamma      = (const float*)d_in[8];
    const float* beta       = (const float*)d_in[9];
    const float* rm         = (const float*)d_in[10];
    const float* rv         = (const float*)d_in[11];
    const float* W2         = (const float*)d_in[12];
    const float* b2         = (const float*)d_in[13];
    float* out = (float*)d_out;

    cudaFuncSetAttribute((const void*)node_kernel,
                         cudaFuncAttributeMaxDynamicSharedMemorySize, 98304);

    void *pb0, *pb1;
    cudaGetSymbolAddress(&pb0, g_buf0);
    cudaGetSymbolAddress(&pb1, g_buf1);
    float* bufs[2] = { (float*)pb0, (float*)pb1 };

    const int edge_blocks = (N_EDGES + EPB - 1) / EPB;
    const int node_blocks = (N_NODES + NT - 1) / NT;
    const int pool_blocks = (N_NODES + PCHUNK - 1) / PCHUNK;

    const float* cur = x;
    for (int l = 0; l < N_LAYERS; l++) {
        edge_kernel<<<edge_blocks, 256>>>(cur, edge_index, edge_attr, W_edge, b_edge, l);
        float* nxt = bufs[l & 1];
        node_kernel<<<node_blocks, 256, 98304>>>(cur, nxt, W1, b1, gamma, beta,
                                                 rm, rv, W2, b2, l,
                                                 (l != N_LAYERS - 1) ? 1 : 0);
        cur = nxt;
    }

    zero_counts_kernel<<<1, 128>>>();
    cudaMemsetAsync(out, 0, (size_t)N_GRAPHS * D * sizeof(float));
    pool_kernel<<<pool_blocks, 128>>>(cur, batch, out);
    div_kernel<<<N_GRAPHS, 128>>>(out);
}